// round 3
// baseline (speedup 1.0000x reference)
#include <cuda_runtime.h>

#define NN 1024
#define EPSF 1e-5f
#define INFF 1e5f

typedef unsigned long long u64;

// ---------------- device scratch (allocation-free rule: __device__ globals) ----
__device__ float g_he[64u * 1024u * 1024u];   // [i][k][j] : (i*64+k)*NN + j  (256MB)
__device__ float g_slog[NN * NN];             // semantic logits (post leaky-relu)
__device__ float g_w[NN * NN];                // combined+normalized attention weight
__device__ float g_A[NN * 64];                // h_i @ ew1[0:64]
__device__ float g_Bt[64 * NN];               // transposed h_j @ ew1[64:128] : [k][j]
__device__ float g_hagg[NN * 64];
__device__ float g_combos[NN * 96];           // [i][c][d], un-normalized sum over j
__device__ float g_xacc[NN * 3];

// ---------------- f32x2 packed helpers ----------------------------------------
__device__ __forceinline__ u64 pk2(float x, float y) {
    u64 r;
    asm("mov.b64 %0,{%1,%2};" : "=l"(r) : "r"(__float_as_uint(x)), "r"(__float_as_uint(y)));
    return r;
}
__device__ __forceinline__ float2 upk2(u64 p) {
    unsigned lo, hi;
    asm("mov.b64 {%0,%1},%2;" : "=r"(lo), "=r"(hi) : "l"(p));
    return make_float2(__uint_as_float(lo), __uint_as_float(hi));
}
__device__ __forceinline__ void fma2(u64& a, u64 x, u64 w) {
    asm("fma.rn.f32x2 %0,%1,%2,%0;" : "+l"(a) : "l"(x), "l"(w));
}

__device__ __forceinline__ float silu_f(float v) { return v / (1.f + __expf(-v)); }

// acc += v (KD regs) * W[KD x RS] (smem row-major), producing NO outputs at col `co`
template <int KD, int NO>
__device__ __forceinline__ void mv_acc(u64* acc, const float* v, const float* W,
                                       int RS, int co) {
#pragma unroll
    for (int kk = 0; kk < KD; kk++) {
        u64 a2 = pk2(v[kk], v[kk]);
        const double2* wr = reinterpret_cast<const double2*>(W + kk * RS + co);
#pragma unroll
        for (int t = 0; t < NO / 4; t++) {
            double2 q = wr[t];
            fma2(acc[2 * t], a2, __double_as_longlong(q.x));
            fma2(acc[2 * t + 1], a2, __double_as_longlong(q.y));
        }
    }
}

template <int KD, int NO>
__device__ __forceinline__ void mv(const float* v, const float* W, int RS, int co,
                                   const float* b, float* out) {
    u64 acc[NO / 2];
#pragma unroll
    for (int t = 0; t < NO / 2; t++)
        acc[t] = b ? pk2(b[co + 2 * t], b[co + 2 * t + 1]) : pk2(0.f, 0.f);
    mv_acc<KD, NO>(acc, v, W, RS, co);
#pragma unroll
    for (int t = 0; t < NO / 2; t++) {
        float2 f = upk2(acc[t]);
        out[2 * t] = f.x;
        out[2 * t + 1] = f.y;
    }
}

// ---------------- block reductions --------------------------------------------
__device__ __forceinline__ float blk_red(float v, float* red, int tid, bool ismax) {
    red[tid] = v;
    __syncthreads();
#pragma unroll
    for (int s = 128; s >= 1; s >>= 1) {
        if (tid < s) red[tid] = ismax ? fmaxf(red[tid], red[tid + s]) : red[tid] + red[tid + s];
        __syncthreads();
    }
    float r = red[0];
    __syncthreads();
    return r;
}

// ---------------- K-zero: reset accumulators ----------------------------------
__global__ void k_zero() {
    int idx = blockIdx.x * blockDim.x + threadIdx.x;
    if (idx < NN * 64) g_hagg[idx] = 0.f;
    if (idx < NN * 96) g_combos[idx] = 0.f;
    if (idx < NN * 3) g_xacc[idx] = 0.f;
}

// ---------------- K0: per-node pre-GEMMs A = h@W1a, Bt = (h@W1b)^T -------------
__global__ void k_node_pre(const float* __restrict__ h, const float* __restrict__ ew1) {
    __shared__ float hr[64];
    int i = blockIdx.x, tid = threadIdx.x;
    hr[tid] = h[i * 64 + tid];
    __syncthreads();
    float a = 0.f, b = 0.f;
#pragma unroll
    for (int m = 0; m < 64; m++) {
        float hm = hr[m];
        a += hm * ew1[m * 64 + tid];
        b += hm * ew1[(64 + m) * 64 + tid];
    }
    g_A[i * 64 + tid] = a;
    g_Bt[tid * NN + i] = b;
}

// ---------------- K1: edge MLP layer2 + semantic logits ------------------------
__global__ void __launch_bounds__(128) k_edge(const float* __restrict__ x,
                                              const float* __restrict__ ew1,
                                              const float* __restrict__ eb1,
                                              const float* __restrict__ ew2,
                                              const float* __restrict__ eb2,
                                              const float* __restrict__ aw,
                                              const float* __restrict__ ab) {
    __shared__ alignas(16) float sW[4096];  // ew2 row-major
    __shared__ float sA[64], sC[64], sB2[64], sAw[64];
    __shared__ float sXi[3];
    __shared__ float sAb;
    int i = blockIdx.y, tid = threadIdx.x;
    int j = blockIdx.x * 128 + tid;

    for (int t = tid; t < 4096; t += 128) sW[t] = ew2[t];
    if (tid < 64) {
        sA[tid] = g_A[i * 64 + tid] + eb1[tid];  // fold b1
        sC[tid] = ew1[128 * 64 + tid];           // w1c (distance row)
        sB2[tid] = eb2[tid];
        sAw[tid] = aw[tid];
    }
    if (tid < 3) sXi[tid] = x[i * 3 + tid];
    if (tid == 0) sAb = ab[0];
    __syncthreads();

    float dx = sXi[0] - x[j * 3 + 0];
    float dy = sXi[1] - x[j * 3 + 1];
    float dz = sXi[2] - x[j * 3 + 2];
    float nrm = sqrtf(dx * dx + dy * dy + dz * dz + EPSF);

    float v[64];
#pragma unroll
    for (int k = 0; k < 64; k++) {
        float z = sA[k] + g_Bt[k * NN + j] + nrm * sC[k];
        v[k] = silu_f(z);
    }

    float slog = sAb;
    int base = (i * 64) * NN + j;
#pragma unroll
    for (int half = 0; half < 2; half++) {
        float he[32];
        mv<64, 32>(v, sW, 64, half * 32, sB2, he);
#pragma unroll
        for (int k = 0; k < 32; k++) {
            g_he[base + (half * 32 + k) * NN] = he[k];
            slog += he[k] * sAw[half * 32 + k];
        }
    }
    slog = (slog > 0.f) ? slog : 0.01f * slog;  // leaky_relu
    g_slog[i * NN + j] = slog;
}

// ---------------- K3: fused euclid+semantic softmax combine --------------------
__global__ void k_attn(const float* __restrict__ x, const float* __restrict__ lg) {
    __shared__ float sls[NN], sle[NN];
    __shared__ float red[256];
    int i = blockIdx.x, tid = threadIdx.x;
    float gamma = __expf(lg[0]);
    float xi0 = x[i * 3 + 0], xi1 = x[i * 3 + 1], xi2 = x[i * 3 + 2];

    for (int j = tid; j < NN; j += 256) {
        float dx = xi0 - x[j * 3 + 0];
        float dy = xi1 - x[j * 3 + 1];
        float dz = xi2 - x[j * 3 + 2];
        float nrm = sqrtf(dx * dx + dy * dy + dz * dz + EPSF);
        float diag = (j == i) ? INFF : 0.f;
        sle[j] = -(nrm + diag) * gamma;
        sls[j] = g_slog[i * NN + j] - diag;
    }
    __syncthreads();

    float m = -3.4e38f;
    for (int j = tid; j < NN; j += 256) m = fmaxf(m, sls[j]);
    m = blk_red(m, red, tid, true);

    float ze = 0.f, zs = 0.f, tt = 0.f;
    for (int j = tid; j < NN; j += 256) {
        float le = sle[j], ls = sls[j] - m;
        ze += __expf(le);
        zs += __expf(ls);
        tt += __expf(le + ls);
    }
    ze = blk_red(ze, red, tid, false);
    zs = blk_red(zs, red, tid, false);
    tt = blk_red(tt, red, tid, false);

    // comb = att_e*att_s / (sum_j att_e*att_s + EPS)  ==  exp(le+ls-m)/(T + EPS*Ze*Zs)
    float inv = 1.f / (tt + EPSF * ze * zs);
    for (int j = tid; j < NN; j += 256)
        g_w[i * NN + j] = __expf(sle[j] + sls[j] - m) * inv;
}

// ---------------- K4: coeff MLP + coordinate MLP + reductions -------------------
__global__ void __launch_bounds__(128) k_pair2(const float* __restrict__ x,
                                               const float* __restrict__ fw1,
                                               const float* __restrict__ fb1,
                                               const float* __restrict__ fw2,
                                               const float* __restrict__ fb2,
                                               const float* __restrict__ cw1,
                                               const float* __restrict__ cb1,
                                               const float* __restrict__ cw2) {
    extern __shared__ float dyn[];
    float* sF1 = dyn;             // 4096
    float* sC1 = dyn + 4096;      // 4096
    float* sF2 = dyn + 8192;      // 2048
    float* sFb1 = dyn + 10240;    // 64
    float* sCb1 = dyn + 10304;    // 64
    float* sCw2 = dyn + 10368;    // 64
    float* sFb2 = dyn + 10432;    // 32
    float* sXi = dyn + 10464;     // 4
    float* buf = dyn + 10468;     // 128*37 = 4736

    int i = blockIdx.y, tid = threadIdx.x;
    int j = blockIdx.x * 128 + tid;

    for (int t = tid; t < 4096; t += 128) { sF1[t] = fw1[t]; sC1[t] = cw1[t]; }
    for (int t = tid; t < 2048; t += 128) sF2[t] = fw2[t];
    if (tid < 64) { sFb1[tid] = fb1[tid]; sCb1[tid] = cb1[tid]; sCw2[tid] = cw2[tid]; }
    if (tid < 32) sFb2[tid] = fb2[tid];
    if (tid < 3) sXi[tid] = x[i * 3 + tid];
    __syncthreads();

    float he[64];
    int base = (i * 64) * NN + j;
#pragma unroll
    for (int k = 0; k < 64; k++) he[k] = g_he[base + k * NN];
    float w = g_w[i * NN + j];

    // ---- phi = silu(h_e@cw1+cb1)@cw2 ----
    float phi = 0.f;
#pragma unroll
    for (int half = 0; half < 2; half++) {
        float u[32];
        mv<64, 32>(he, sC1, 64, half * 32, sCb1, u);
#pragma unroll
        for (int k = 0; k < 32; k++) phi += silu_f(u[k]) * sCw2[half * 32 + k];
    }

    // ---- coeff = silu(w*(h_e@fw1)+fb1)@fw2 + fb2 ----
    u64 cacc[16];
#pragma unroll
    for (int t = 0; t < 16; t++) cacc[t] = pk2(sFb2[2 * t], sFb2[2 * t + 1]);
#pragma unroll
    for (int q = 0; q < 4; q++) {
        float sc[16];
        mv<64, 16>(he, sF1, 64, q * 16, nullptr, sc);
#pragma unroll
        for (int k = 0; k < 16; k++) sc[k] = silu_f(w * sc[k] + sFb1[q * 16 + k]);
        mv_acc<16, 32>(cacc, sc, sF2 + q * 16 * 32, 32, 0);
    }
    float coeff[32];
#pragma unroll
    for (int t = 0; t < 16; t++) {
        float2 f = upk2(cacc[t]);
        coeff[2 * t] = f.x;
        coeff[2 * t + 1] = f.y;
    }

    // ---- geometry ----
    float dxr0 = sXi[0] - x[j * 3 + 0];
    float dxr1 = sXi[1] - x[j * 3 + 1];
    float dxr2 = sXi[2] - x[j * 3 + 2];
    float nrm = sqrtf(dxr0 * dxr0 + dxr1 * dxr1 + dxr2 * dxr2 + EPSF);
    float inv1 = 1.f / (nrm + 1.f);

    // ---- h_agg = sum_j w * h_e (column reduce via smem staging) ----
#pragma unroll
    for (int half = 0; half < 2; half++) {
#pragma unroll
        for (int c = 0; c < 32; c++) buf[tid * 37 + c] = w * he[half * 32 + c];
        __syncthreads();
        if (tid < 32) {
            float s = 0.f;
            for (int jj = 0; jj < 128; jj++) s += buf[jj * 37 + tid];
            atomicAdd(&g_hagg[i * 64 + half * 32 + tid], s);
        }
        __syncthreads();
    }

    // ---- combos + x accumulators ----
#pragma unroll
    for (int c = 0; c < 32; c++) buf[tid * 37 + c] = coeff[c];
    buf[tid * 37 + 32] = dxr0;
    buf[tid * 37 + 33] = dxr1;
    buf[tid * 37 + 34] = dxr2;
    buf[tid * 37 + 35] = phi;
    buf[tid * 37 + 36] = inv1;
    __syncthreads();
    if (tid < 96) {
        int c = tid / 3, d = tid % 3;
        float s = 0.f;
        for (int jj = 0; jj < 128; jj++)
            s += buf[jj * 37 + c] * (buf[jj * 37 + 32 + d] * buf[jj * 37 + 36]);
        atomicAdd(&g_combos[i * 96 + c * 3 + d], s);
    } else if (tid < 99) {
        int d = tid - 96;
        float s = 0.f;
        for (int jj = 0; jj < 128; jj++) s += buf[jj * 37 + 32 + d] * buf[jj * 37 + 35];
        atomicAdd(&g_xacc[i * 3 + d], s);
    }
}

// ---------------- K6: node-level MLPs + outputs --------------------------------
__global__ void k_final(const float* __restrict__ h, const float* __restrict__ x,
                        const float* __restrict__ nw1, const float* __restrict__ nb1,
                        const float* __restrict__ nw2, const float* __restrict__ nb2,
                        const float* __restrict__ pw1, const float* __restrict__ pb1,
                        const float* __restrict__ pw2, const float* __restrict__ pb2,
                        float* __restrict__ out, int write_x) {
    __shared__ float sq[32], p1[64], nin[192], n1[64];
    int i = blockIdx.x, tid = threadIdx.x;
    if (tid < 32) {
        float s = 0.f;
#pragma unroll
        for (int d = 0; d < 3; d++) {
            float v = g_combos[i * 96 + tid * 3 + d] * (1.f / 1024.f);
            s += v * v;
        }
        sq[tid] = s;
    }
    __syncthreads();
    {
        float a = pb1[tid];
#pragma unroll
        for (int c = 0; c < 32; c++) a += sq[c] * pw1[c * 64 + tid];
        p1[tid] = silu_f(a);
    }
    __syncthreads();
    {
        float a = pb2[tid];
#pragma unroll
        for (int m = 0; m < 64; m++) a += p1[m] * pw2[m * 64 + tid];
        nin[128 + tid] = a;                     // h_comb
        nin[tid] = h[i * 64 + tid];             // h
        nin[64 + tid] = g_hagg[i * 64 + tid];   // h_agg
    }
    __syncthreads();
    {
        float a = nb1[tid];
#pragma unroll
        for (int m = 0; m < 192; m++) a += nin[m] * nw1[m * 64 + tid];
        n1[tid] = silu_f(a);
    }
    __syncthreads();
    {
        float a = nb2[tid];
#pragma unroll
        for (int m = 0; m < 64; m++) a += n1[m] * nw2[m * 64 + tid];
        out[i * 64 + tid] = h[i * 64 + tid] + a;
    }
    if (write_x && tid < 3)
        out[NN * 64 + i * 3 + tid] = x[i * 3 + tid] + g_xacc[i * 3 + tid] * (1.f / 1024.f);
}

// ---------------- host ----------------------------------------------------------
extern "C" void kernel_launch(void* const* d_in, const int* in_sizes, int n_in,
                              void* d_out, int out_size) {
    const float* h = (const float*)d_in[0];
    const float* x = (const float*)d_in[1];
    const float* ew1 = (const float*)d_in[2];
    const float* eb1 = (const float*)d_in[3];
    const float* ew2 = (const float*)d_in[4];
    const float* eb2 = (const float*)d_in[5];
    const float* nw1 = (const float*)d_in[6];
    const float* nb1 = (const float*)d_in[7];
    const float* nw2 = (const float*)d_in[8];
    const float* nb2 = (const float*)d_in[9];
    const float* cw1 = (const float*)d_in[10];
    const float* cb1 = (const float*)d_in[11];
    const float* cw2 = (const float*)d_in[12];
    const float* aw = (const float*)d_in[13];
    const float* ab = (const float*)d_in[14];
    const float* fw1 = (const float*)d_in[15];
    const float* fb1 = (const float*)d_in[16];
    const float* fw2 = (const float*)d_in[17];
    const float* fb2 = (const float*)d_in[18];
    const float* pw1 = (const float*)d_in[19];
    const float* pb1 = (const float*)d_in[20];
    const float* pw2 = (const float*)d_in[21];
    const float* pb2 = (const float*)d_in[22];
    const float* lg = (const float*)d_in[23];
    float* out = (float*)d_out;

    const int K4_SMEM = (10468 + 128 * 37) * sizeof(float);  // 60816 B
    cudaFuncSetAttribute(k_pair2, cudaFuncAttributeMaxDynamicSharedMemorySize, K4_SMEM);

    int write_x = (out_size >= NN * 64 + NN * 3) ? 1 : 0;

    k_zero<<<(NN * 96 + 255) / 256, 256>>>();
    k_node_pre<<<NN, 64>>>(h, ew1);
    k_edge<<<dim3(NN / 128, NN), 128>>>(x, ew1, eb1, ew2, eb2, aw, ab);
    k_attn<<<NN, 256>>>(x, lg);
    k_pair2<<<dim3(NN / 128, NN), 128, K4_SMEM>>>(x, fw1, fb1, fw2, fb2, cw1, cb1, cw2);
    k_final<<<NN, 64>>>(h, x, nw1, nb1, nw2, nb2, pw1, pb1, pw2, pb2, out, write_x);
}

// round 4
// speedup vs baseline: 1.4728x; 1.4728x over previous
#include <cuda_runtime.h>

#define NN 1024
#define EPSF 1e-5f
#define INFF 1e5f

typedef unsigned long long u64;

// ---------------- device scratch (allocation-free rule) -------------------------
__device__ __align__(16) float g_A[NN * 64];    // h@ew1[0:64] + eb1, node-major
__device__ __align__(16) float g_B[NN * 64];    // h@ew1[64:128], node-major [j][k]
__device__ float g_slog[NN * NN];               // semantic logits (post leaky-relu)
__device__ float g_w[NN * NN];                  // combined normalized attention weight
__device__ float g_wsum[NN];                    // sum_j comb
__device__ float g_cv[NN * 64];                 // sum_j comb * v   (for h_agg fold)
__device__ float g_combos[NN * 96];             // [i][c][d] un-normalized
__device__ float g_xacc[NN * 3];
// folded weights
__device__ __align__(16) float g_Wc[4096];      // ew2@cw1
__device__ __align__(16) float g_Wf1[4096];     // ew2@fw1
__device__ float g_bc[64];                      // eb2@cw1 + cb1
__device__ float g_bf1a[64];                    // eb2@fw1
__device__ float g_waw[64];                     // ew2@aw
__device__ float g_baw[1];                      // eb2.aw + ab
__device__ float g_Cw[64];                      // ew1 row 128 (distance weights)

// ---------------- f32x2 packed helpers ------------------------------------------
__device__ __forceinline__ u64 pk2(float x, float y) {
    u64 r;
    asm("mov.b64 %0,{%1,%2};" : "=l"(r) : "r"(__float_as_uint(x)), "r"(__float_as_uint(y)));
    return r;
}
__device__ __forceinline__ float2 upk2(u64 p) {
    unsigned lo, hi;
    asm("mov.b64 {%0,%1},%2;" : "=r"(lo), "=r"(hi) : "l"(p));
    return make_float2(__uint_as_float(lo), __uint_as_float(hi));
}
__device__ __forceinline__ void fma2(u64& a, u64 x, u64 w) {
    asm("fma.rn.f32x2 %0,%1,%2,%0;" : "+l"(a) : "l"(x), "l"(w));
}

// silu via EX2 + RCP.approx (2 MUFU, no IEEE-div slow path)
__device__ __forceinline__ float silu_f(float v) {
    return __fdividef(v, 1.f + __expf(-v));
}

// acc += v (KD regs) * W[KD x RS] (smem row-major), NO outputs at column co
template <int KD, int NO>
__device__ __forceinline__ void mv_acc(u64* acc, const float* v, const float* W,
                                       int RS, int co) {
#pragma unroll
    for (int kk = 0; kk < KD; kk++) {
        u64 a2 = pk2(v[kk], v[kk]);
        const double2* wr = reinterpret_cast<const double2*>(W + kk * RS + co);
#pragma unroll
        for (int t = 0; t < NO / 4; t++) {
            double2 q = wr[t];
            fma2(acc[2 * t], a2, __double_as_longlong(q.x));
            fma2(acc[2 * t + 1], a2, __double_as_longlong(q.y));
        }
    }
}

template <int KD, int NO>
__device__ __forceinline__ void mv(const float* v, const float* W, int RS, int co,
                                   const float* b, float* out) {
    u64 acc[NO / 2];
#pragma unroll
    for (int t = 0; t < NO / 2; t++)
        acc[t] = b ? pk2(b[co + 2 * t], b[co + 2 * t + 1]) : pk2(0.f, 0.f);
    mv_acc<KD, NO>(acc, v, W, RS, co);
#pragma unroll
    for (int t = 0; t < NO / 2; t++) {
        float2 f = upk2(acc[t]);
        out[2 * t] = f.x;
        out[2 * t + 1] = f.y;
    }
}

__device__ __forceinline__ float blk_red(float v, float* red, int tid, bool ismax) {
    red[tid] = v;
    __syncthreads();
#pragma unroll
    for (int s = 128; s >= 1; s >>= 1) {
        if (tid < s) red[tid] = ismax ? fmaxf(red[tid], red[tid + s]) : red[tid] + red[tid + s];
        __syncthreads();
    }
    float r = red[0];
    __syncthreads();
    return r;
}

// ---------------- K-zero ---------------------------------------------------------
__global__ void k_zero() {
    int idx = blockIdx.x * blockDim.x + threadIdx.x;
    if (idx < NN * 64) g_cv[idx] = 0.f;
    if (idx < NN * 96) g_combos[idx] = 0.f;
    if (idx < NN * 3) g_xacc[idx] = 0.f;
}

// ---------------- k_fold: fold small weights through ew2 -------------------------
__global__ void k_fold(const float* __restrict__ ew1, const float* __restrict__ ew2,
                       const float* __restrict__ eb2, const float* __restrict__ cw1,
                       const float* __restrict__ cb1, const float* __restrict__ fw1,
                       const float* __restrict__ aw, const float* __restrict__ ab) {
    __shared__ float sE[4096];
    int tid = threadIdx.x;  // 64 threads
    for (int t = tid; t < 4096; t += 64) sE[t] = ew2[t];
    __syncthreads();
    for (int m = 0; m < 64; m++) {
        float ac = 0.f, af = 0.f;
        for (int k = 0; k < 64; k++) {
            float e = sE[m * 64 + k];
            ac += e * cw1[k * 64 + tid];
            af += e * fw1[k * 64 + tid];
        }
        g_Wc[m * 64 + tid] = ac;
        g_Wf1[m * 64 + tid] = af;
    }
    float sw = 0.f;
    for (int k = 0; k < 64; k++) sw += sE[tid * 64 + k] * aw[k];
    g_waw[tid] = sw;
    float bc = cb1[tid], bf = 0.f;
    for (int k = 0; k < 64; k++) {
        bc += eb2[k] * cw1[k * 64 + tid];
        bf += eb2[k] * fw1[k * 64 + tid];
    }
    g_bc[tid] = bc;
    g_bf1a[tid] = bf;
    g_Cw[tid] = ew1[128 * 64 + tid];
    if (tid == 0) {
        float b = ab[0];
        for (int k = 0; k < 64; k++) b += eb2[k] * aw[k];
        g_baw[0] = b;
    }
}

// ---------------- K0: per-node first-layer GEMVs ---------------------------------
__global__ void k_node_pre(const float* __restrict__ h, const float* __restrict__ ew1,
                           const float* __restrict__ eb1) {
    __shared__ float hr[64];
    int i = blockIdx.x, tid = threadIdx.x;
    hr[tid] = h[i * 64 + tid];
    __syncthreads();
    float a = eb1[tid], b = 0.f;
#pragma unroll
    for (int m = 0; m < 64; m++) {
        float hm = hr[m];
        a += hm * ew1[m * 64 + tid];
        b += hm * ew1[(64 + m) * 64 + tid];
    }
    g_A[i * 64 + tid] = a;       // eb1 folded
    g_B[i * 64 + tid] = b;       // node-major for float4 loads
}

// ---------------- K1: pass-1, semantic logits only -------------------------------
__global__ void __launch_bounds__(256) k_edge1(const float* __restrict__ x) {
    __shared__ float sA[64], sC[64], sW[64], sXi[3], sBaw[1];
    int i = blockIdx.y, tid = threadIdx.x;
    int j = blockIdx.x * 256 + tid;
    if (tid < 64) {
        sA[tid] = g_A[i * 64 + tid];
        sC[tid] = g_Cw[tid];
        sW[tid] = g_waw[tid];
    }
    if (tid < 3) sXi[tid] = x[i * 3 + tid];
    if (tid == 0) sBaw[0] = g_baw[0];
    __syncthreads();

    float dx = sXi[0] - x[j * 3 + 0];
    float dy = sXi[1] - x[j * 3 + 1];
    float dz = sXi[2] - x[j * 3 + 2];
    float nrm = sqrtf(dx * dx + dy * dy + dz * dz + EPSF);

    const float4* B4 = reinterpret_cast<const float4*>(g_B + j * 64);
    float slog = sBaw[0];
#pragma unroll
    for (int t = 0; t < 16; t++) {
        float4 b = B4[t];
        slog += silu_f(sA[4 * t + 0] + b.x + nrm * sC[4 * t + 0]) * sW[4 * t + 0];
        slog += silu_f(sA[4 * t + 1] + b.y + nrm * sC[4 * t + 1]) * sW[4 * t + 1];
        slog += silu_f(sA[4 * t + 2] + b.z + nrm * sC[4 * t + 2]) * sW[4 * t + 2];
        slog += silu_f(sA[4 * t + 3] + b.w + nrm * sC[4 * t + 3]) * sW[4 * t + 3];
    }
    slog = (slog > 0.f) ? slog : 0.01f * slog;
    g_slog[i * NN + j] = slog;
}

// ---------------- K3: fused softmax combine --------------------------------------
__global__ void k_attn(const float* __restrict__ x, const float* __restrict__ lg) {
    __shared__ float sls[NN], sle[NN];
    __shared__ float red[256];
    int i = blockIdx.x, tid = threadIdx.x;
    float gamma = __expf(lg[0]);
    float xi0 = x[i * 3 + 0], xi1 = x[i * 3 + 1], xi2 = x[i * 3 + 2];

    for (int j = tid; j < NN; j += 256) {
        float dx = xi0 - x[j * 3 + 0];
        float dy = xi1 - x[j * 3 + 1];
        float dz = xi2 - x[j * 3 + 2];
        float nrm = sqrtf(dx * dx + dy * dy + dz * dz + EPSF);
        float diag = (j == i) ? INFF : 0.f;
        sle[j] = -(nrm + diag) * gamma;
        sls[j] = g_slog[i * NN + j] - diag;
    }
    __syncthreads();

    float m = -3.4e38f;
    for (int j = tid; j < NN; j += 256) m = fmaxf(m, sls[j]);
    m = blk_red(m, red, tid, true);

    float ze = 0.f, zs = 0.f, tt = 0.f;
    for (int j = tid; j < NN; j += 256) {
        float le = sle[j], ls = sls[j] - m;
        ze += __expf(le);
        zs += __expf(ls);
        tt += __expf(le + ls);
    }
    ze = blk_red(ze, red, tid, false);
    zs = blk_red(zs, red, tid, false);
    tt = blk_red(tt, red, tid, false);

    float inv = 1.f / (tt + EPSF * ze * zs);
    for (int j = tid; j < NN; j += 256)
        g_w[i * NN + j] = __expf(sle[j] + sls[j] - m) * inv;
    if (tid == 0) g_wsum[i] = tt * inv;
}

// ---------------- K4: fused pair kernel (phi + coeff + all reductions) -----------
__global__ void __launch_bounds__(128) k_pair(const float* __restrict__ x,
                                              const float* __restrict__ fw2,
                                              const float* __restrict__ fb1,
                                              const float* __restrict__ fb2,
                                              const float* __restrict__ cw2) {
    extern __shared__ float dyn[];
    float* sWc = dyn;              // 4096
    float* sWf1 = dyn + 4096;      // 4096
    float* sF2 = dyn + 8192;       // 2048
    float* sbc = dyn + 10240;      // 64
    float* sbf1a = dyn + 10304;    // 64
    float* sfb1 = dyn + 10368;     // 64
    float* scw2 = dyn + 10432;     // 64
    float* sA = dyn + 10496;       // 64
    float* sC = dyn + 10560;       // 64
    float* sfb2 = dyn + 10624;     // 32
    float* sXi = dyn + 10656;      // 4
    float* buf = dyn + 10660;      // 128*37

    int i = blockIdx.y, tid = threadIdx.x;
    int j = blockIdx.x * 128 + tid;

    for (int t = tid; t < 4096; t += 128) { sWc[t] = g_Wc[t]; sWf1[t] = g_Wf1[t]; }
    for (int t = tid; t < 2048; t += 128) sF2[t] = fw2[t];
    if (tid < 64) {
        sbc[tid] = g_bc[tid]; sbf1a[tid] = g_bf1a[tid]; sfb1[tid] = fb1[tid];
        scw2[tid] = cw2[tid]; sA[tid] = g_A[i * 64 + tid]; sC[tid] = g_Cw[tid];
    }
    if (tid < 32) sfb2[tid] = fb2[tid];
    if (tid < 3) sXi[tid] = x[i * 3 + tid];
    __syncthreads();

    // geometry
    float dxr0 = sXi[0] - x[j * 3 + 0];
    float dxr1 = sXi[1] - x[j * 3 + 1];
    float dxr2 = sXi[2] - x[j * 3 + 2];
    float nrm = sqrtf(dxr0 * dxr0 + dxr1 * dxr1 + dxr2 * dxr2 + EPSF);
    float inv1 = __fdividef(1.f, nrm + 1.f);

    // recompute v (first edge layer + silu)
    float v[64];
    {
        const float4* B4 = reinterpret_cast<const float4*>(g_B + j * 64);
#pragma unroll
        for (int t = 0; t < 16; t++) {
            float4 b = B4[t];
            v[4 * t + 0] = silu_f(sA[4 * t + 0] + b.x + nrm * sC[4 * t + 0]);
            v[4 * t + 1] = silu_f(sA[4 * t + 1] + b.y + nrm * sC[4 * t + 1]);
            v[4 * t + 2] = silu_f(sA[4 * t + 2] + b.z + nrm * sC[4 * t + 2]);
            v[4 * t + 3] = silu_f(sA[4 * t + 3] + b.w + nrm * sC[4 * t + 3]);
        }
    }
    float w = g_w[i * NN + j];

    // ---- phi = silu(v@Wc + bc)@cw2 ----
    float phi = 0.f;
#pragma unroll
    for (int q = 0; q < 4; q++) {
        float u[16];
        mv<64, 16>(v, sWc, 64, q * 16, sbc, u);
#pragma unroll
        for (int k = 0; k < 16; k++) phi += silu_f(u[k]) * scw2[q * 16 + k];
    }

    // ---- coeff = silu(w*(v@Wf1 + bf1a) + fb1)@fw2 + fb2 ----
    u64 cacc[16];
#pragma unroll
    for (int t = 0; t < 16; t++) cacc[t] = pk2(sfb2[2 * t], sfb2[2 * t + 1]);
#pragma unroll
    for (int q = 0; q < 4; q++) {
        float tq[16];
        mv<64, 16>(v, sWf1, 64, q * 16, nullptr, tq);
        float s[16];
#pragma unroll
        for (int k = 0; k < 16; k++)
            s[k] = silu_f(w * (tq[k] + sbf1a[q * 16 + k]) + sfb1[q * 16 + k]);
        mv_acc<16, 32>(cacc, s, sF2 + q * 16 * 32, 32, 0);
    }
    float coeff[32];
#pragma unroll
    for (int t = 0; t < 16; t++) {
        float2 f = upk2(cacc[t]);
        coeff[2 * t] = f.x;
        coeff[2 * t + 1] = f.y;
    }

    // ---- cv = sum_j w * v ----
#pragma unroll
    for (int half = 0; half < 2; half++) {
#pragma unroll
        for (int c = 0; c < 32; c++) buf[tid * 37 + c] = w * v[half * 32 + c];
        __syncthreads();
        if (tid < 32) {
            float s = 0.f;
            for (int jj = 0; jj < 128; jj++) s += buf[jj * 37 + tid];
            atomicAdd(&g_cv[i * 64 + half * 32 + tid], s);
        }
        __syncthreads();
    }

    // ---- combos + x accumulators ----
#pragma unroll
    for (int c = 0; c < 32; c++) buf[tid * 37 + c] = coeff[c];
    buf[tid * 37 + 32] = dxr0;
    buf[tid * 37 + 33] = dxr1;
    buf[tid * 37 + 34] = dxr2;
    buf[tid * 37 + 35] = phi;
    buf[tid * 37 + 36] = inv1;
    __syncthreads();
    if (tid < 96) {
        int c = tid / 3, d = tid % 3;
        float s = 0.f;
        for (int jj = 0; jj < 128; jj++)
            s += buf[jj * 37 + c] * (buf[jj * 37 + 32 + d] * buf[jj * 37 + 36]);
        atomicAdd(&g_combos[i * 96 + c * 3 + d], s);
    } else if (tid < 99) {
        int d = tid - 96;
        float s = 0.f;
        for (int jj = 0; jj < 128; jj++) s += buf[jj * 37 + 32 + d] * buf[jj * 37 + 35];
        atomicAdd(&g_xacc[i * 3 + d], s);
    }
}

// ---------------- K6: node-level MLPs + outputs ----------------------------------
__global__ void k_final(const float* __restrict__ h, const float* __restrict__ x,
                        const float* __restrict__ ew2, const float* __restrict__ eb2,
                        const float* __restrict__ nw1, const float* __restrict__ nb1,
                        const float* __restrict__ nw2, const float* __restrict__ nb2,
                        const float* __restrict__ pw1, const float* __restrict__ pb1,
                        const float* __restrict__ pw2, const float* __restrict__ pb2,
                        float* __restrict__ out, int write_x) {
    __shared__ float sq[32], p1[64], nin[192], n1[64], scv[64];
    int i = blockIdx.x, tid = threadIdx.x;
    scv[tid] = g_cv[i * 64 + tid];
    if (tid < 32) {
        float s = 0.f;
#pragma unroll
        for (int d = 0; d < 3; d++) {
            float cvv = g_combos[i * 96 + tid * 3 + d] * (1.f / 1024.f);
            s += cvv * cvv;
        }
        sq[tid] = s;
    }
    __syncthreads();
    {
        // h_agg = cv @ ew2 + wsum*eb2
        float a = g_wsum[i] * eb2[tid];
#pragma unroll
        for (int m = 0; m < 64; m++) a += scv[m] * ew2[m * 64 + tid];
        nin[64 + tid] = a;
        float b = pb1[tid];
#pragma unroll
        for (int c = 0; c < 32; c++) b += sq[c] * pw1[c * 64 + tid];
        p1[tid] = silu_f(b);
        nin[tid] = h[i * 64 + tid];
    }
    __syncthreads();
    {
        float a = pb2[tid];
#pragma unroll
        for (int m = 0; m < 64; m++) a += p1[m] * pw2[m * 64 + tid];
        nin[128 + tid] = a;  // h_comb
    }
    __syncthreads();
    {
        float a = nb1[tid];
#pragma unroll
        for (int m = 0; m < 192; m++) a += nin[m] * nw1[m * 64 + tid];
        n1[tid] = silu_f(a);
    }
    __syncthreads();
    {
        float a = nb2[tid];
#pragma unroll
        for (int m = 0; m < 64; m++) a += n1[m] * nw2[m * 64 + tid];
        out[i * 64 + tid] = h[i * 64 + tid] + a;
    }
    if (write_x && tid < 3)
        out[NN * 64 + i * 3 + tid] = x[i * 3 + tid] + g_xacc[i * 3 + tid] * (1.f / 1024.f);
}

// ---------------- host ------------------------------------------------------------
extern "C" void kernel_launch(void* const* d_in, const int* in_sizes, int n_in,
                              void* d_out, int out_size) {
    const float* h = (const float*)d_in[0];
    const float* x = (const float*)d_in[1];
    const float* ew1 = (const float*)d_in[2];
    const float* eb1 = (const float*)d_in[3];
    const float* ew2 = (const float*)d_in[4];
    const float* eb2 = (const float*)d_in[5];
    const float* nw1 = (const float*)d_in[6];
    const float* nb1 = (const float*)d_in[7];
    const float* nw2 = (const float*)d_in[8];
    const float* nb2 = (const float*)d_in[9];
    const float* cw1 = (const float*)d_in[10];
    const float* cb1 = (const float*)d_in[11];
    const float* cw2 = (const float*)d_in[12];
    const float* aw = (const float*)d_in[13];
    const float* ab = (const float*)d_in[14];
    const float* fw1 = (const float*)d_in[15];
    const float* fb1 = (const float*)d_in[16];
    const float* fw2 = (const float*)d_in[17];
    const float* fb2 = (const float*)d_in[18];
    const float* pw1 = (const float*)d_in[19];
    const float* pb1 = (const float*)d_in[20];
    const float* pw2 = (const float*)d_in[21];
    const float* pb2 = (const float*)d_in[22];
    const float* lg = (const float*)d_in[23];
    float* out = (float*)d_out;

    const int K4_SMEM = (10660 + 128 * 37) * sizeof(float);  // 61584 B
    cudaFuncSetAttribute(k_pair, cudaFuncAttributeMaxDynamicSharedMemorySize, K4_SMEM);

    int write_x = (out_size >= NN * 64 + NN * 3) ? 1 : 0;

    k_zero<<<(NN * 96 + 255) / 256, 256>>>();
    k_fold<<<1, 64>>>(ew1, ew2, eb2, cw1, cb1, fw1, aw, ab);
    k_node_pre<<<NN, 64>>>(h, ew1, eb1);
    k_edge1<<<dim3(NN / 256, NN), 256>>>(x);
    k_attn<<<NN, 256>>>(x, lg);
    k_pair<<<dim3(NN / 128, NN), 128, K4_SMEM>>>(x, fw2, fb1, fb2, cw2);
    k_final<<<NN, 64>>>(h, x, ew2, eb2, nw1, nb1, nw2, nb2, pw1, pb1, pw2, pb2, out, write_x);
}

// round 5
// speedup vs baseline: 2.1594x; 1.4662x over previous
#include <cuda_runtime.h>

#define NN 1024
#define EPSF 1e-5f
#define INFF 1e5f

typedef unsigned long long u64;

// ---------------- device scratch --------------------------------------------------
__device__ float g_A[NN * 64];                  // h@ew1[0:64] + eb1, node-major
__device__ float g_Bt[64 * NN];                 // h@ew1[64:128], k-major [k][j]
__device__ float g_slog[NN * NN];
__device__ float g_w[NN * NN];
__device__ float g_wsum[NN];
__device__ float g_cv[NN * 64];
__device__ float g_combos[NN * 96];
__device__ float g_xacc[NN * 3];
// folded weights
__device__ __align__(16) float g_Wcf[64 * 128]; // row k: [ew2@cw1 row | ew2@fw1 row]
__device__ float g_bc[64];                      // eb2@cw1 + cb1
__device__ float g_bf1a[64];                    // eb2@fw1
__device__ float g_waw[64];                     // ew2@aw
__device__ float g_baw[1];                      // eb2.aw + ab
__device__ float g_Cw[64];                      // ew1 row 128

// ---------------- f32x2 helpers ---------------------------------------------------
__device__ __forceinline__ u64 pk2(float x, float y) {
    u64 r;
    asm("mov.b64 %0,{%1,%2};" : "=l"(r) : "r"(__float_as_uint(x)), "r"(__float_as_uint(y)));
    return r;
}
__device__ __forceinline__ float2 upk2(u64 p) {
    unsigned lo, hi;
    asm("mov.b64 {%0,%1},%2;" : "=r"(lo), "=r"(hi) : "l"(p));
    return make_float2(__uint_as_float(lo), __uint_as_float(hi));
}
__device__ __forceinline__ void fma2(u64& a, u64 x, u64 w) {
    asm("fma.rn.f32x2 %0,%1,%2,%0;" : "+l"(a) : "l"(x), "l"(w));
}
__device__ __forceinline__ float silu_f(float v) {
    return __fdividef(v, 1.f + __expf(-v));
}

__device__ __forceinline__ float blk_red(float v, float* red, int tid, bool ismax) {
    red[tid] = v;
    __syncthreads();
#pragma unroll
    for (int s = 128; s >= 1; s >>= 1) {
        if (tid < s) red[tid] = ismax ? fmaxf(red[tid], red[tid + s]) : red[tid] + red[tid + s];
        __syncthreads();
    }
    float r = red[0];
    __syncthreads();
    return r;
}

// ---------------- K-zero ----------------------------------------------------------
__global__ void k_zero() {
    int idx = blockIdx.x * blockDim.x + threadIdx.x;
    if (idx < NN * 64) g_cv[idx] = 0.f;
    if (idx < NN * 96) g_combos[idx] = 0.f;
    if (idx < NN * 3) g_xacc[idx] = 0.f;
}

// ---------------- k_fold: 65 blocks -----------------------------------------------
__global__ void k_fold(const float* __restrict__ ew1, const float* __restrict__ ew2,
                       const float* __restrict__ eb2, const float* __restrict__ cw1,
                       const float* __restrict__ cb1, const float* __restrict__ fw1,
                       const float* __restrict__ aw, const float* __restrict__ ab) {
    int b = blockIdx.x, tid = threadIdx.x;  // 64 threads
    if (b < 64) {
        __shared__ float se[64];
        se[tid] = ew2[b * 64 + tid];
        __syncthreads();
        float ac = 0.f, af = 0.f;
#pragma unroll 8
        for (int k = 0; k < 64; k++) {
            float e = se[k];
            ac += e * cw1[k * 64 + tid];
            af += e * fw1[k * 64 + tid];
        }
        g_Wcf[b * 128 + tid] = ac;
        g_Wcf[b * 128 + 64 + tid] = af;
    } else {
        float sw = 0.f;
        for (int k = 0; k < 64; k++) sw += ew2[tid * 64 + k] * aw[k];
        g_waw[tid] = sw;
        float bc = cb1[tid], bf = 0.f;
        for (int k = 0; k < 64; k++) {
            bc += eb2[k] * cw1[k * 64 + tid];
            bf += eb2[k] * fw1[k * 64 + tid];
        }
        g_bc[tid] = bc;
        g_bf1a[tid] = bf;
        g_Cw[tid] = ew1[128 * 64 + tid];
        if (tid == 0) {
            float s = ab[0];
            for (int k = 0; k < 64; k++) s += eb2[k] * aw[k];
            g_baw[0] = s;
        }
    }
}

// ---------------- K0: per-node first-layer GEMVs ----------------------------------
__global__ void k_node_pre(const float* __restrict__ h, const float* __restrict__ ew1,
                           const float* __restrict__ eb1) {
    __shared__ float hr[64];
    int i = blockIdx.x, tid = threadIdx.x;
    hr[tid] = h[i * 64 + tid];
    __syncthreads();
    float a = eb1[tid], b = 0.f;
#pragma unroll 8
    for (int m = 0; m < 64; m++) {
        float hm = hr[m];
        a += hm * ew1[m * 64 + tid];
        b += hm * ew1[(64 + m) * 64 + tid];
    }
    g_A[i * 64 + tid] = a;
    g_Bt[tid * NN + i] = b;   // k-major
}

// ---------------- K1: semantic logits ---------------------------------------------
__global__ void __launch_bounds__(256) k_edge1(const float* __restrict__ x) {
    __shared__ float sA[64], sC[64], sW[64], sXi[3], sBaw[1];
    int i = blockIdx.y, tid = threadIdx.x;
    int j = blockIdx.x * 256 + tid;
    if (tid < 64) {
        sA[tid] = g_A[i * 64 + tid];
        sC[tid] = g_Cw[tid];
        sW[tid] = g_waw[tid];
    }
    if (tid < 3) sXi[tid] = x[i * 3 + tid];
    if (tid == 0) sBaw[0] = g_baw[0];
    __syncthreads();

    float dx = sXi[0] - x[j * 3 + 0];
    float dy = sXi[1] - x[j * 3 + 1];
    float dz = sXi[2] - x[j * 3 + 2];
    float nrm = sqrtf(dx * dx + dy * dy + dz * dz + EPSF);

    float slog = sBaw[0];
#pragma unroll 8
    for (int k = 0; k < 64; k++) {
        float b = g_Bt[k * NN + j];                       // coalesced
        slog += silu_f(sA[k] + b + nrm * sC[k]) * sW[k];
    }
    slog = (slog > 0.f) ? slog : 0.01f * slog;
    g_slog[i * NN + j] = slog;
}

// ---------------- K3: fused softmax combine ---------------------------------------
__global__ void k_attn(const float* __restrict__ x, const float* __restrict__ lg) {
    __shared__ float sls[NN], sle[NN];
    __shared__ float red[256];
    int i = blockIdx.x, tid = threadIdx.x;
    float gamma = __expf(lg[0]);
    float xi0 = x[i * 3 + 0], xi1 = x[i * 3 + 1], xi2 = x[i * 3 + 2];

    for (int j = tid; j < NN; j += 256) {
        float dx = xi0 - x[j * 3 + 0];
        float dy = xi1 - x[j * 3 + 1];
        float dz = xi2 - x[j * 3 + 2];
        float nrm = sqrtf(dx * dx + dy * dy + dz * dz + EPSF);
        float diag = (j == i) ? INFF : 0.f;
        sle[j] = -(nrm + diag) * gamma;
        sls[j] = g_slog[i * NN + j] - diag;
    }
    __syncthreads();

    float m = -3.4e38f;
    for (int j = tid; j < NN; j += 256) m = fmaxf(m, sls[j]);
    m = blk_red(m, red, tid, true);

    float ze = 0.f, zs = 0.f, tt = 0.f;
    for (int j = tid; j < NN; j += 256) {
        float le = sle[j], ls = sls[j] - m;
        ze += __expf(le);
        zs += __expf(ls);
        tt += __expf(le + ls);
    }
    ze = blk_red(ze, red, tid, false);
    zs = blk_red(zs, red, tid, false);
    tt = blk_red(tt, red, tid, false);

    float inv = 1.f / (tt + EPSF * ze * zs);
    for (int j = tid; j < NN; j += 256)
        g_w[i * NN + j] = __expf(sle[j] + sls[j] - m) * inv;
    if (tid == 0) g_wsum[i] = tt * inv;
}

// ---------------- K4: fused pair kernel -------------------------------------------
// smem layout (floats):
#define OFF_SV   0          // 64 x 261  (reused as staging rows 0..38 at end)
#define SVS      261
#define OFF_W    16704      // g_Wcf copy: 64 x 128
#define OFF_F2   24896      // fw2: 64 x 32
#define OFF_SWT  26944      // w per j-local (256)
#define OFF_BC   27200
#define OFF_BF   27264
#define OFF_FB1  27328
#define OFF_CW2  27392
#define OFF_A    27456
#define OFF_C    27520
#define OFF_FB2  27584
#define OFF_XI   27616
#define OFF_CVP  27620      // 64 x 4 partials
#define K4_FLOATS 27876

__global__ void __launch_bounds__(256, 2) k_pair(const float* __restrict__ x,
                                                 const float* __restrict__ fw2,
                                                 const float* __restrict__ fb1,
                                                 const float* __restrict__ fb2,
                                                 const float* __restrict__ cw2) {
    extern __shared__ __align__(16) float dyn[];
    float* sv = dyn + OFF_SV;
    float* sW = dyn + OFF_W;
    float* sF2 = dyn + OFF_F2;
    float* swt = dyn + OFF_SWT;

    int i = blockIdx.y, tid = threadIdx.x;
    int j = blockIdx.x * 256 + tid;

    for (int t = tid; t < 8192; t += 256) sW[t] = g_Wcf[t];
    for (int t = tid; t < 2048; t += 256) sF2[t] = fw2[t];
    if (tid < 64) {
        dyn[OFF_BC + tid] = g_bc[tid];
        dyn[OFF_BF + tid] = g_bf1a[tid];
        dyn[OFF_FB1 + tid] = fb1[tid];
        dyn[OFF_CW2 + tid] = cw2[tid];
        dyn[OFF_A + tid] = g_A[i * 64 + tid];
        dyn[OFF_C + tid] = g_Cw[tid];
    }
    if (tid < 32) dyn[OFF_FB2 + tid] = fb2[tid];
    if (tid < 3) dyn[OFF_XI + tid] = x[i * 3 + tid];
    __syncthreads();

    // ---- phase A: geometry + v into smem (coalesced g_Bt loads) ----
    float dxr0 = dyn[OFF_XI + 0] - x[j * 3 + 0];
    float dxr1 = dyn[OFF_XI + 1] - x[j * 3 + 1];
    float dxr2 = dyn[OFF_XI + 2] - x[j * 3 + 2];
    float nrm = sqrtf(dxr0 * dxr0 + dxr1 * dxr1 + dxr2 * dxr2 + EPSF);
    float inv1 = __fdividef(1.f, nrm + 1.f);
    float w = g_w[i * NN + j];
    swt[tid] = w;

#pragma unroll 8
    for (int k = 0; k < 64; k++) {
        float b = g_Bt[k * NN + j];
        sv[k * SVS + tid] = silu_f(dyn[OFF_A + k] + b + nrm * dyn[OFF_C + k]);
    }

    // ---- phase B: fused Wc/Wf1 GEMVs + second layers ----
    float phi = 0.f;
    u64 cacc[16];
#pragma unroll
    for (int t = 0; t < 16; t++) cacc[t] = pk2(dyn[OFF_FB2 + 2 * t], dyn[OFF_FB2 + 2 * t + 1]);

    for (int q = 0; q < 4; q++) {
        u64 tqc[8], tqf[8];
#pragma unroll
        for (int t = 0; t < 8; t++) { tqc[t] = pk2(0.f, 0.f); tqf[t] = pk2(0.f, 0.f); }
#pragma unroll 8
        for (int kk = 0; kk < 64; kk++) {
            float vk = sv[kk * SVS + tid];
            u64 a2 = pk2(vk, vk);
            const double2* wc = reinterpret_cast<const double2*>(sW + kk * 128 + q * 16);
            const double2* wf = reinterpret_cast<const double2*>(sW + kk * 128 + 64 + q * 16);
#pragma unroll
            for (int t = 0; t < 4; t++) {
                double2 qc = wc[t];
                fma2(tqc[2 * t], a2, __double_as_longlong(qc.x));
                fma2(tqc[2 * t + 1], a2, __double_as_longlong(qc.y));
                double2 qf = wf[t];
                fma2(tqf[2 * t], a2, __double_as_longlong(qf.x));
                fma2(tqf[2 * t + 1], a2, __double_as_longlong(qf.y));
            }
        }
        float s[16];
#pragma unroll
        for (int t = 0; t < 8; t++) {
            float2 fc = upk2(tqc[t]);
            phi += silu_f(fc.x + dyn[OFF_BC + q * 16 + 2 * t]) * dyn[OFF_CW2 + q * 16 + 2 * t];
            phi += silu_f(fc.y + dyn[OFF_BC + q * 16 + 2 * t + 1]) * dyn[OFF_CW2 + q * 16 + 2 * t + 1];
            float2 ff = upk2(tqf[t]);
            s[2 * t] = silu_f(w * (ff.x + dyn[OFF_BF + q * 16 + 2 * t]) + dyn[OFF_FB1 + q * 16 + 2 * t]);
            s[2 * t + 1] = silu_f(w * (ff.y + dyn[OFF_BF + q * 16 + 2 * t + 1]) + dyn[OFF_FB1 + q * 16 + 2 * t + 1]);
        }
        // cacc += s @ fw2[q*16 : q*16+16, :]
        const float* F2q = sF2 + q * 16 * 32;
#pragma unroll
        for (int kk = 0; kk < 16; kk++) {
            u64 a2 = pk2(s[kk], s[kk]);
            const double2* wr = reinterpret_cast<const double2*>(F2q + kk * 32);
#pragma unroll
            for (int t = 0; t < 8; t++) {
                double2 qv = wr[t];
                fma2(cacc[2 * t], a2, __double_as_longlong(qv.x));
                fma2(cacc[2 * t + 1], a2, __double_as_longlong(qv.y));
            }
        }
    }
    float coeff[32];
#pragma unroll
    for (int t = 0; t < 16; t++) {
        float2 f = upk2(cacc[t]);
        coeff[2 * t] = f.x;
        coeff[2 * t + 1] = f.y;
    }

    // ---- epilogue 1: cv = sum_j w*v  (parallel column reduce) ----
    __syncthreads();
    {
        int k = tid & 63, qq = tid >> 6;
        const float* vp = sv + k * SVS + qq * 64;
        const float* wp = swt + qq * 64;
        float sacc = 0.f;
#pragma unroll 8
        for (int jj = 0; jj < 64; jj++) sacc += wp[jj] * vp[jj];
        dyn[OFF_CVP + k * 4 + qq] = sacc;
    }
    __syncthreads();
    if (tid < 64) {
        const float4 p = *reinterpret_cast<const float4*>(dyn + OFF_CVP + tid * 4);
        atomicAdd(&g_cv[i * 64 + tid], p.x + p.y + p.z + p.w);
    }

    // ---- epilogue 2: stage coeff/dir/dxr/phi into sv region ----
    __syncthreads();
#pragma unroll
    for (int c = 0; c < 32; c++) sv[c * SVS + tid] = coeff[c];
    sv[32 * SVS + tid] = dxr0 * inv1;
    sv[33 * SVS + tid] = dxr1 * inv1;
    sv[34 * SVS + tid] = dxr2 * inv1;
    sv[35 * SVS + tid] = dxr0;
    sv[36 * SVS + tid] = dxr1;
    sv[37 * SVS + tid] = dxr2;
    sv[38 * SVS + tid] = phi;
    __syncthreads();

    if (tid < 96) {
        int c = tid / 3, d = tid % 3;
        const float* cp = sv + c * SVS;
        const float* dp = sv + (32 + d) * SVS;
        float sacc = 0.f;
#pragma unroll 8
        for (int jj = 0; jj < 256; jj++) sacc += cp[jj] * dp[jj];
        atomicAdd(&g_combos[i * 96 + c * 3 + d], sacc);
    } else if (tid < 99) {
        int d = tid - 96;
        const float* dp = sv + (35 + d) * SVS;
        const float* pp = sv + 38 * SVS;
        float sacc = 0.f;
#pragma unroll 8
        for (int jj = 0; jj < 256; jj++) sacc += dp[jj] * pp[jj];
        atomicAdd(&g_xacc[i * 3 + d], sacc);
    }
}

// ---------------- K6: node-level MLPs + outputs -----------------------------------
__global__ void k_final(const float* __restrict__ h, const float* __restrict__ x,
                        const float* __restrict__ ew2, const float* __restrict__ eb2,
                        const float* __restrict__ nw1, const float* __restrict__ nb1,
                        const float* __restrict__ nw2, const float* __restrict__ nb2,
                        const float* __restrict__ pw1, const float* __restrict__ pb1,
                        const float* __restrict__ pw2, const float* __restrict__ pb2,
                        float* __restrict__ out, int write_x) {
    __shared__ float sq[32], p1[64], nin[192], n1[64], scv[64];
    int i = blockIdx.x, tid = threadIdx.x;
    scv[tid] = g_cv[i * 64 + tid];
    if (tid < 32) {
        float s = 0.f;
#pragma unroll
        for (int d = 0; d < 3; d++) {
            float cvv = g_combos[i * 96 + tid * 3 + d] * (1.f / 1024.f);
            s += cvv * cvv;
        }
        sq[tid] = s;
    }
    __syncthreads();
    {
        float a = g_wsum[i] * eb2[tid];
#pragma unroll 8
        for (int m = 0; m < 64; m++) a += scv[m] * ew2[m * 64 + tid];
        nin[64 + tid] = a;
        float b = pb1[tid];
#pragma unroll
        for (int c = 0; c < 32; c++) b += sq[c] * pw1[c * 64 + tid];
        p1[tid] = silu_f(b);
        nin[tid] = h[i * 64 + tid];
    }
    __syncthreads();
    {
        float a = pb2[tid];
#pragma unroll 8
        for (int m = 0; m < 64; m++) a += p1[m] * pw2[m * 64 + tid];
        nin[128 + tid] = a;
    }
    __syncthreads();
    {
        float a = nb1[tid];
#pragma unroll 8
        for (int m = 0; m < 192; m++) a += nin[m] * nw1[m * 64 + tid];
        n1[tid] = silu_f(a);
    }
    __syncthreads();
    {
        float a = nb2[tid];
#pragma unroll 8
        for (int m = 0; m < 64; m++) a += n1[m] * nw2[m * 64 + tid];
        out[i * 64 + tid] = h[i * 64 + tid] + a;
    }
    if (write_x && tid < 3)
        out[NN * 64 + i * 3 + tid] = x[i * 3 + tid] + g_xacc[i * 3 + tid] * (1.f / 1024.f);
}

// ---------------- host -------------------------------------------------------------
extern "C" void kernel_launch(void* const* d_in, const int* in_sizes, int n_in,
                              void* d_out, int out_size) {
    const float* h = (const float*)d_in[0];
    const float* x = (const float*)d_in[1];
    const float* ew1 = (const float*)d_in[2];
    const float* eb1 = (const float*)d_in[3];
    const float* ew2 = (const float*)d_in[4];
    const float* eb2 = (const float*)d_in[5];
    const float* nw1 = (const float*)d_in[6];
    const float* nb1 = (const float*)d_in[7];
    const float* nw2 = (const float*)d_in[8];
    const float* nb2 = (const float*)d_in[9];
    const float* cw1 = (const float*)d_in[10];
    const float* cb1 = (const float*)d_in[11];
    const float* cw2 = (const float*)d_in[12];
    const float* aw = (const float*)d_in[13];
    const float* ab = (const float*)d_in[14];
    const float* fw1 = (const float*)d_in[15];
    const float* fb1 = (const float*)d_in[16];
    const float* fw2 = (const float*)d_in[17];
    const float* fb2 = (const float*)d_in[18];
    const float* pw1 = (const float*)d_in[19];
    const float* pb1 = (const float*)d_in[20];
    const float* pw2 = (const float*)d_in[21];
    const float* pb2 = (const float*)d_in[22];
    const float* lg = (const float*)d_in[23];
    float* out = (float*)d_out;

    const int K4_SMEM = K4_FLOATS * sizeof(float);  // 111504 B
    cudaFuncSetAttribute(k_pair, cudaFuncAttributeMaxDynamicSharedMemorySize, K4_SMEM);

    int write_x = (out_size >= NN * 64 + NN * 3) ? 1 : 0;

    k_zero<<<(NN * 96 + 255) / 256, 256>>>();
    k_fold<<<65, 64>>>(ew1, ew2, eb2, cw1, cb1, fw1, aw, ab);
    k_node_pre<<<NN, 64>>>(h, ew1, eb1);
    k_edge1<<<dim3(NN / 256, NN), 256>>>(x);
    k_attn<<<NN, 256>>>(x, lg);
    k_pair<<<dim3(NN / 256, NN), 256, K4_SMEM>>>(x, fw2, fb1, fb2, cw2);
    k_final<<<NN, 64>>>(h, x, ew2, eb2, nw1, nb1, nw2, nb2, pw1, pb1, pw2, pb2, out, write_x);
}